// round 13
// baseline (speedup 1.0000x reference)
#include <cuda_runtime.h>
#include <cuda_bf16.h>
#include <cstdint>

// Problem constants
#define SEQ  2048
#define HID  1024
#define NH   16
#define HD   64
#define QKVN (3 * HID)   // 3072

// Scratch (allocation-free rule: __device__ globals)
__device__ float g_qkv[SEQ * QKVN];        // [2048, 3072]  (tf32-rounded values)
__device__ float g_attn[SEQ * HID];        // [2048, 1024]  (tf32-rounded values)
__device__ float g_xr[SEQ * HID];          // x rounded to tf32
__device__ float g_war[HID * QKVN];        // w_attn rounded to tf32
__device__ float g_wpr[HID * HID];         // w_proj rounded to tf32

// ===========================================================================
// Helpers
// ===========================================================================
__device__ __forceinline__ uint32_t smem_u32(const void* p) {
    uint32_t a;
    asm("{ .reg .u64 t; cvta.to.shared.u64 t, %1; cvt.u32.u64 %0, t; }" : "=r"(a) : "l"(p));
    return a;
}
__device__ __forceinline__ uint32_t f2tf32(float v) {
    uint32_t r;
    asm("cvt.rna.tf32.f32 %0, %1;" : "=r"(r) : "f"(v));
    return r;
}
__device__ __forceinline__ float tf32v(float v) {
    return __uint_as_float(f2tf32(v));
}
__device__ __forceinline__ void mma_tf32(float d[4],
                                         uint32_t a0, uint32_t a1, uint32_t a2, uint32_t a3,
                                         uint32_t b0, uint32_t b1) {
    asm volatile(
        "mma.sync.aligned.m16n8k8.row.col.f32.tf32.tf32.f32 "
        "{%0,%1,%2,%3}, {%4,%5,%6,%7}, {%8,%9}, {%0,%1,%2,%3};"
        : "+f"(d[0]), "+f"(d[1]), "+f"(d[2]), "+f"(d[3])
        : "r"(a0), "r"(a1), "r"(a2), "r"(a3), "r"(b0), "r"(b1));
}
#define CP_ASYNC16(dst_u32, src_ptr) \
    asm volatile("cp.async.cg.shared.global [%0], [%1], 16;" :: "r"(dst_u32), "l"(src_ptr))
#define CP_COMMIT() asm volatile("cp.async.commit_group;" ::: "memory")
#define CP_WAIT1()  asm volatile("cp.async.wait_group 1;" ::: "memory")
#define CP_WAIT0()  asm volatile("cp.async.wait_group 0;" ::: "memory")

// ===========================================================================
// Fused elementwise tf32 rounding for x / w_attn / w_proj (one launch)
// ===========================================================================
#define XR_N4  (SEQ * HID / 4)
#define WAR_N4 (HID * QKVN / 4)
#define WPR_N4 (HID * HID / 4)
#define ROUND_TOTAL4 (XR_N4 + WAR_N4 + WPR_N4)

__global__ __launch_bounds__(256) void round3_tf32(
    const float* __restrict__ a, float* __restrict__ ar,
    const float* __restrict__ b, float* __restrict__ br,
    const float* __restrict__ c, float* __restrict__ cr)
{
    int i = blockIdx.x * 256 + threadIdx.x;
    const float* src; float* dst; int idx;
    if (i < XR_N4)                 { src = a; dst = ar; idx = i; }
    else if (i < XR_N4 + WAR_N4)   { src = b; dst = br; idx = i - XR_N4; }
    else if (i < ROUND_TOTAL4)     { src = c; dst = cr; idx = i - XR_N4 - WAR_N4; }
    else return;
    float4 v = *(const float4*)(src + (size_t)idx * 4);
    float4 w;
    w.x = tf32v(v.x); w.y = tf32v(v.y); w.z = tf32v(v.z); w.w = tf32v(v.w);
    *(float4*)(dst + (size_t)idx * 4) = w;
}

// ===========================================================================
// tf32 mma.sync GEMM, templated CTA N-tile: C = A @ B + bias (B row-major).
// CTA tile 64 x BN, 128 threads (4 warps 2x2), warp tile 32 x BN/2.
// 2-stage cp.async double buffer (proven). 4 CTAs/SM via 128-reg cap.
// BN=128 for QKV (grid 768), BN=64 for proj (grid 512, single wave).
// Per-output accumulation order identical across BN -> bit-identical result.
// ===========================================================================
#define LDA 36
#define A_STAGE (64 * LDA)      // floats

template<int BN>
__global__ __launch_bounds__(128, 4)
void gemm_tf32(const float* __restrict__ A, const float* __restrict__ B,
               const float* __restrict__ bias, float* __restrict__ C,
               int M, int N, int K, int round_out)
{
    constexpr int LDB = BN + 8;
    constexpr int B_STAGE = 32 * LDB;
    constexpr int NT = BN / 16;          // n-fragments per warp
    constexpr int F4 = BN / 4;           // float4 per B row
    constexpr int BU = (32 * F4) / 128;  // B copy iters per thread

    extern __shared__ float smem[];
    float* As = smem;                      // [2][A_STAGE]
    float* Bs = smem + 2 * A_STAGE;        // [2][B_STAGE]
    const uint32_t as_u32 = smem_u32(As);
    const uint32_t bs_u32 = smem_u32(Bs);

    const int tid  = threadIdx.x;
    const int wid  = tid >> 5;
    const int lane = tid & 31;
    const int g = lane >> 2;
    const int t = lane & 3;
    const int wy = wid >> 1;                // 0..1 (M)
    const int wx = wid & 1;                 // 0..1 (N)
    const int row0 = blockIdx.y * 64;
    const int col0 = blockIdx.x * BN;
    const int NS = K >> 5;

    const float* Ag = A + (size_t)row0 * K;
    const float* Bg = B + col0;

    auto copy_stage = [&](int s, int buf) {
        const int k0 = s * 32;
        // A: 64 rows x 8 float4 = 512 -> 4 per thread
#pragma unroll
        for (int u = 0; u < 4; u++) {
            int idx = u * 128 + tid;
            int row = idx >> 3;
            int c4  = idx & 7;
            CP_ASYNC16(as_u32 + (buf * A_STAGE + row * LDA + c4 * 4) * 4,
                       Ag + (size_t)row * K + k0 + c4 * 4);
        }
        // B: 32 rows x F4 float4 -> BU per thread
#pragma unroll
        for (int u = 0; u < BU; u++) {
            int idx = u * 128 + tid;
            int row = idx / F4;
            int c4  = idx % F4;
            CP_ASYNC16(bs_u32 + (buf * B_STAGE + row * LDB + c4 * 4) * 4,
                       Bg + (size_t)(k0 + row) * N + c4 * 4);
        }
    };

    float acc[2][NT][4];
#pragma unroll
    for (int mt = 0; mt < 2; mt++)
#pragma unroll
        for (int nt = 0; nt < NT; nt++)
#pragma unroll
            for (int r = 0; r < 4; r++) acc[mt][nt][r] = 0.f;

    copy_stage(0, 0);
    CP_COMMIT();

    for (int s = 0; s < NS; s++) {
        const int buf = s & 1;
        if (s + 1 < NS) {
            copy_stage(s + 1, buf ^ 1);
            CP_COMMIT();
            CP_WAIT1();
        } else {
            CP_WAIT0();
        }
        __syncthreads();

        const float* Ab = As + buf * A_STAGE;
        const float* Bb = Bs + buf * B_STAGE;

#pragma unroll
        for (int ks = 0; ks < 4; ks++) {
            const int kk = ks * 8;
            uint32_t af[2][4];
#pragma unroll
            for (int mt = 0; mt < 2; mt++) {
                const float* pa = Ab + (wy * 32 + mt * 16 + g) * LDA + kk + t;
                af[mt][0] = __float_as_uint(pa[0]);
                af[mt][1] = __float_as_uint(pa[8 * LDA]);
                af[mt][2] = __float_as_uint(pa[4]);
                af[mt][3] = __float_as_uint(pa[8 * LDA + 4]);
            }
            uint32_t bf[NT][2];
#pragma unroll
            for (int nt = 0; nt < NT; nt++) {
                const float* pb = Bb + (kk + t) * LDB + wx * (BN / 2) + nt * 8 + g;
                bf[nt][0] = __float_as_uint(pb[0]);
                bf[nt][1] = __float_as_uint(pb[4 * LDB]);
            }
#pragma unroll
            for (int mt = 0; mt < 2; mt++)
#pragma unroll
                for (int nt = 0; nt < NT; nt++)
                    mma_tf32(acc[mt][nt], af[mt][0], af[mt][1], af[mt][2], af[mt][3],
                             bf[nt][0], bf[nt][1]);
        }
        __syncthreads();
    }

#pragma unroll
    for (int mt = 0; mt < 2; mt++) {
        int m = row0 + wy * 32 + mt * 16 + g;
#pragma unroll
        for (int nt = 0; nt < NT; nt++) {
            int n = col0 + wx * (BN / 2) + nt * 8 + 2 * t;
            float2 o0, o1;
            o0.x = acc[mt][nt][0] + bias[n];
            o0.y = acc[mt][nt][1] + bias[n + 1];
            o1.x = acc[mt][nt][2] + bias[n];
            o1.y = acc[mt][nt][3] + bias[n + 1];
            if (round_out) {
                o0.x = tf32v(o0.x); o0.y = tf32v(o0.y);
                o1.x = tf32v(o1.x); o1.y = tf32v(o1.y);
            }
            *(float2*)(C + (size_t)m * N + n)       = o0;
            *(float2*)(C + (size_t)(m + 8) * N + n) = o1;
        }
    }
}

#define GEMM_SMEM_128 ((2 * (A_STAGE + 32 * 136)) * 4)
#define GEMM_SMEM_64  ((2 * (A_STAGE + 32 * 72)) * 4)

// ===========================================================================
// Flash attention, tf32 mma.sync, PREFETCHED k-loop.
// CTA = (head, 64 q rows), 4 warps. Q persistent fragments, shfl-transposed P.
// K single-buffered (free after S-phase), V double-buffered: K(kb+1)/V(kb+1)
// issued right after the post-S barrier so loads overlap softmax + PV.
// Smem 108.5KB -> 2 CTAs/SM (217KB <= 228KB).
// ===========================================================================
#define ALD 68                       // K lead dim (S-phase B reads: bank 4g+t)
#define VLD 72                       // V lead dim (PV B reads: bank 8t+g)
#define K_FLOATS (128 * ALD)         // K tile (also Q staging area before loop)
#define V_FLOATS (128 * VLD)
#define ATTN_FLOATS (K_FLOATS + 2 * V_FLOATS)
#define ATTN_BYTES  (ATTN_FLOATS * 4)

__global__ __launch_bounds__(128)
void attn_mma(const float* __restrict__ qkv, float* __restrict__ out)
{
    extern __shared__ float sm[];
    float* KPs = sm;                     // K tile (Q staged here before loop)
    float* Vb[2] = { sm + K_FLOATS, sm + K_FLOATS + V_FLOATS };
    const uint32_t kp_u32 = smem_u32(KPs);
    const uint32_t v_u32[2] = { smem_u32(Vb[0]), smem_u32(Vb[1]) };

    const int tid  = threadIdx.x;
    const int lane = tid & 31;
    const int wid  = tid >> 5;     // 0..3
    const int g = lane >> 2;
    const int t = lane & 3;
    const int h  = blockIdx.y;
    const int qb = (int)gridDim.x - 1 - (int)blockIdx.x;   // heavy CTAs first
    const int q0 = qb * 64;
    const int rowbase = wid * 16;
    const int nkb = (qb >> 1) + 1;

    // ---- stage Q into KPs (x0.125 exponent-only: stays valid tf32) ----
#pragma unroll
    for (int u = 0; u < 8; u++) {
        int i4 = u * 128 + tid;
        int r = i4 >> 4;
        int d = (i4 & 15) * 4;
        float4 v = *(const float4*)(qkv + (size_t)(q0 + r) * QKVN + h * HD + d);
        v.x *= 0.125f; v.y *= 0.125f; v.z *= 0.125f; v.w *= 0.125f;
        *(float4*)&KPs[r * ALD + d] = v;
    }
    __syncthreads();

    uint32_t qf[8][4];
#pragma unroll
    for (int ks = 0; ks < 8; ks++) {
        const float* pa = KPs + (rowbase + g) * ALD + ks * 8 + t;
        qf[ks][0] = __float_as_uint(pa[0]);
        qf[ks][1] = __float_as_uint(pa[8 * ALD]);
        qf[ks][2] = __float_as_uint(pa[4]);
        qf[ks][3] = __float_as_uint(pa[8 * ALD + 4]);
    }
    __syncthreads();   // qf reads done before K(0) overwrites the staging area

    // ---- issue loads for k-block 0 ----
    auto issue_kv = [&](int kb, int vbuf) {
#pragma unroll
        for (int u = 0; u < 16; u++) {
            int i4 = u * 128 + tid;
            int r = i4 >> 4;
            int d = (i4 & 15) * 4;
            const float* base = qkv + (size_t)(kb * 128 + r) * QKVN + h * HD;
            CP_ASYNC16(kp_u32 + (r * ALD + d) * 4, base + HID + d);
            CP_ASYNC16(v_u32[vbuf] + (r * VLD + d) * 4, base + 2 * HID + d);
        }
        CP_COMMIT();
    };
    issue_kv(0, 0);

    float O[8][4];
    float m0 = -1e30f, m1 = -1e30f, l0 = 0.f, l1 = 0.f;
#pragma unroll
    for (int nt = 0; nt < 8; nt++)
#pragma unroll
        for (int r = 0; r < 4; r++) O[nt][r] = 0.f;

    for (int kb = 0; kb < nkb; kb++) {
        CP_WAIT0();
        __syncthreads();   // K(kb)/V(kb) visible; prior V-buffer readers done

        // ---- S = Q @ K^T ----
        float S[16][4];
#pragma unroll
        for (int nt = 0; nt < 16; nt++)
#pragma unroll
            for (int r = 0; r < 4; r++) S[nt][r] = 0.f;

#pragma unroll
        for (int ks = 0; ks < 8; ks++) {
#pragma unroll
            for (int nt = 0; nt < 16; nt++) {
                const float* pb = KPs + (nt * 8 + g) * ALD + ks * 8 + t;
                uint32_t b0 = __float_as_uint(pb[0]);
                uint32_t b1 = __float_as_uint(pb[4]);
                mma_tf32(S[nt], qf[ks][0], qf[ks][1], qf[ks][2], qf[ks][3], b0, b1);
            }
        }

        __syncthreads();   // all warps done reading K(kb)
        if (kb + 1 < nkb)  // prefetch next K/V; overlaps softmax + PV below
            issue_kv(kb + 1, (kb + 1) & 1);

        // ---- causal mask (last k-block only) ----
        if (kb == nkb - 1) {
            const int r0 = q0 + rowbase + g, r1 = r0 + 8;
            const int cb = kb * 128;
#pragma unroll
            for (int nt = 0; nt < 16; nt++) {
                int c = cb + nt * 8 + 2 * t;
                if (c     > r0) S[nt][0] = -1e30f;
                if (c + 1 > r0) S[nt][1] = -1e30f;
                if (c     > r1) S[nt][2] = -1e30f;
                if (c + 1 > r1) S[nt][3] = -1e30f;
            }
        }

        // ---- online softmax ----
        float mt0 = -1e30f, mt1 = -1e30f;
#pragma unroll
        for (int nt = 0; nt < 16; nt++) {
            mt0 = fmaxf(mt0, fmaxf(S[nt][0], S[nt][1]));
            mt1 = fmaxf(mt1, fmaxf(S[nt][2], S[nt][3]));
        }
        mt0 = fmaxf(mt0, __shfl_xor_sync(0xffffffffu, mt0, 1));
        mt0 = fmaxf(mt0, __shfl_xor_sync(0xffffffffu, mt0, 2));
        mt1 = fmaxf(mt1, __shfl_xor_sync(0xffffffffu, mt1, 1));
        mt1 = fmaxf(mt1, __shfl_xor_sync(0xffffffffu, mt1, 2));
        float mn0 = fmaxf(m0, mt0), mn1 = fmaxf(m1, mt1);
        float al0 = __expf(m0 - mn0), al1 = __expf(m1 - mn1);
        float ps0 = 0.f, ps1 = 0.f;
#pragma unroll
        for (int nt = 0; nt < 16; nt++) {
            float p00 = __expf(S[nt][0] - mn0);
            float p01 = __expf(S[nt][1] - mn0);
            float p10 = __expf(S[nt][2] - mn1);
            float p11 = __expf(S[nt][3] - mn1);
            S[nt][0] = p00; S[nt][1] = p01; S[nt][2] = p10; S[nt][3] = p11;
            ps0 += p00 + p01;
            ps1 += p10 + p11;
        }
        ps0 += __shfl_xor_sync(0xffffffffu, ps0, 1);
        ps0 += __shfl_xor_sync(0xffffffffu, ps0, 2);
        ps1 += __shfl_xor_sync(0xffffffffu, ps1, 1);
        ps1 += __shfl_xor_sync(0xffffffffu, ps1, 2);
        l0 = l0 * al0 + ps0;  m0 = mn0;
        l1 = l1 * al1 + ps1;  m1 = mn1;
#pragma unroll
        for (int nt = 0; nt < 8; nt++) {
            O[nt][0] *= al0; O[nt][1] *= al0;
            O[nt][2] *= al1; O[nt][3] *= al1;
        }

        // ---- O += P @ V : A-frag via shfl transpose of S (no smem, no sync) ----
        {
            const float* Vs = Vb[kb & 1];
            const int src0 = (lane & 28) | (t >> 1);
            const int src1 = src0 | 2;
            const bool odd = (t & 1);
#pragma unroll
            for (int ks = 0; ks < 16; ks++) {
                float p0 = tf32v(S[ks][0]), p1 = tf32v(S[ks][1]);
                float p2 = tf32v(S[ks][2]), p3 = tf32v(S[ks][3]);
                float v00 = __shfl_sync(0xffffffffu, p0, src0);
                float v01 = __shfl_sync(0xffffffffu, p1, src0);
                float v02 = __shfl_sync(0xffffffffu, p2, src0);
                float v03 = __shfl_sync(0xffffffffu, p3, src0);
                float v10 = __shfl_sync(0xffffffffu, p0, src1);
                float v11 = __shfl_sync(0xffffffffu, p1, src1);
                float v12 = __shfl_sync(0xffffffffu, p2, src1);
                float v13 = __shfl_sync(0xffffffffu, p3, src1);
                uint32_t a0 = __float_as_uint(odd ? v01 : v00);
                uint32_t a1 = __float_as_uint(odd ? v03 : v02);
                uint32_t a2 = __float_as_uint(odd ? v11 : v10);
                uint32_t a3 = __float_as_uint(odd ? v13 : v12);
#pragma unroll
                for (int nt = 0; nt < 8; nt++) {
                    uint32_t b0 = __float_as_uint(Vs[(ks * 8 + t)     * VLD + nt * 8 + g]);
                    uint32_t b1 = __float_as_uint(Vs[(ks * 8 + t + 4) * VLD + nt * 8 + g]);
                    mma_tf32(O[nt], a0, a1, a2, a3, b0, b1);
                }
            }
        }
    }

    // ---- epilogue: normalize, round to tf32 (feeds proj GEMM) ----
    float inv0 = 1.0f / l0, inv1 = 1.0f / l1;
#pragma unroll
    for (int nt = 0; nt < 8; nt++) {
        int c = h * HD + nt * 8 + 2 * t;
        float2 o0, o1;
        o0.x = tf32v(O[nt][0] * inv0); o0.y = tf32v(O[nt][1] * inv0);
        o1.x = tf32v(O[nt][2] * inv1); o1.y = tf32v(O[nt][3] * inv1);
        *(float2*)(out + (size_t)(q0 + rowbase + g)     * HID + c) = o0;
        *(float2*)(out + (size_t)(q0 + rowbase + g + 8) * HID + c) = o1;
    }
}

// ---------------------------------------------------------------------------
// Launch
// ---------------------------------------------------------------------------
extern "C" void kernel_launch(void* const* d_in, const int* in_sizes, int n_in,
                              void* d_out, int out_size)
{
    const float* x      = (const float*)d_in[0];
    const float* w_attn = (const float*)d_in[1];
    const float* b_attn = (const float*)d_in[2];
    const float* w_proj = (const float*)d_in[3];
    const float* b_proj = (const float*)d_in[4];
    float* out = (float*)d_out;

    float *qkv_p, *attn_p, *xr_p, *war_p, *wpr_p;
    cudaGetSymbolAddress((void**)&qkv_p,  g_qkv);
    cudaGetSymbolAddress((void**)&attn_p, g_attn);
    cudaGetSymbolAddress((void**)&xr_p,   g_xr);
    cudaGetSymbolAddress((void**)&war_p,  g_war);
    cudaGetSymbolAddress((void**)&wpr_p,  g_wpr);

    cudaFuncSetAttribute(attn_mma,
                         cudaFuncAttributeMaxDynamicSharedMemorySize, ATTN_BYTES);
    cudaFuncSetAttribute(gemm_tf32<128>,
                         cudaFuncAttributeMaxDynamicSharedMemorySize, GEMM_SMEM_128);
    cudaFuncSetAttribute(gemm_tf32<64>,
                         cudaFuncAttributeMaxDynamicSharedMemorySize, GEMM_SMEM_64);

    // 0) pre-round inputs to tf32 (single fused launch)
    round3_tf32<<<(ROUND_TOTAL4 + 255) / 256, 256>>>(
        x, xr_p, w_attn, war_p, w_proj, wpr_p);

    // 1) QKV = Xr @ W_attn_r + b_attn     [2048, 3072]  (epilogue rounds to tf32)
    gemm_tf32<128><<<dim3(QKVN / 128, SEQ / 64), 128, GEMM_SMEM_128>>>(
        xr_p, war_p, b_attn, qkv_p, SEQ, QKVN, HID, 1);

    // 2) causal flash attention -> g_attn [2048, 1024]  (epilogue rounds to tf32)
    attn_mma<<<dim3(SEQ / 64, NH), 128, ATTN_BYTES>>>(qkv_p, attn_p);

    // 3) out = attn @ W_proj_r + b_proj   [2048, 1024]  (64x64 tile: single wave)
    gemm_tf32<64><<<dim3(HID / 64, SEQ / 64), 128, GEMM_SMEM_64>>>(
        attn_p, wpr_p, b_proj, out, SEQ, HID, HID, 0);
}

// round 14
// speedup vs baseline: 1.0095x; 1.0095x over previous
#include <cuda_runtime.h>
#include <cuda_bf16.h>
#include <cstdint>

// Problem constants
#define SEQ  2048
#define HID  1024
#define NH   16
#define HD   64
#define QKVN (3 * HID)   // 3072

// Scratch (allocation-free rule: __device__ globals)
__device__ float g_qkv[SEQ * QKVN];        // [2048, 3072]  (tf32-rounded values)
__device__ float g_attn[SEQ * HID];        // [2048, 1024]  (tf32-rounded values)
__device__ float g_xr[SEQ * HID];          // x rounded to tf32
__device__ float g_war[HID * QKVN];        // w_attn rounded to tf32
__device__ float g_wpr[HID * HID];         // w_proj rounded to tf32

// ===========================================================================
// Helpers
// ===========================================================================
__device__ __forceinline__ uint32_t smem_u32(const void* p) {
    uint32_t a;
    asm("{ .reg .u64 t; cvta.to.shared.u64 t, %1; cvt.u32.u64 %0, t; }" : "=r"(a) : "l"(p));
    return a;
}
__device__ __forceinline__ uint32_t f2tf32(float v) {
    uint32_t r;
    asm("cvt.rna.tf32.f32 %0, %1;" : "=r"(r) : "f"(v));
    return r;
}
__device__ __forceinline__ float tf32v(float v) {
    return __uint_as_float(f2tf32(v));
}
__device__ __forceinline__ void mma_tf32(float d[4],
                                         uint32_t a0, uint32_t a1, uint32_t a2, uint32_t a3,
                                         uint32_t b0, uint32_t b1) {
    asm volatile(
        "mma.sync.aligned.m16n8k8.row.col.f32.tf32.tf32.f32 "
        "{%0,%1,%2,%3}, {%4,%5,%6,%7}, {%8,%9}, {%0,%1,%2,%3};"
        : "+f"(d[0]), "+f"(d[1]), "+f"(d[2]), "+f"(d[3])
        : "r"(a0), "r"(a1), "r"(a2), "r"(a3), "r"(b0), "r"(b1));
}
#define CP_ASYNC16(dst_u32, src_ptr) \
    asm volatile("cp.async.cg.shared.global [%0], [%1], 16;" :: "r"(dst_u32), "l"(src_ptr))
#define CP_COMMIT() asm volatile("cp.async.commit_group;" ::: "memory")
#define CP_WAIT1()  asm volatile("cp.async.wait_group 1;" ::: "memory")
#define CP_WAIT0()  asm volatile("cp.async.wait_group 0;" ::: "memory")

// ===========================================================================
// Fused elementwise tf32 rounding for x / w_attn / w_proj (one launch)
// ===========================================================================
#define XR_N4  (SEQ * HID / 4)
#define WAR_N4 (HID * QKVN / 4)
#define WPR_N4 (HID * HID / 4)
#define ROUND_TOTAL4 (XR_N4 + WAR_N4 + WPR_N4)

__global__ __launch_bounds__(256) void round3_tf32(
    const float* __restrict__ a, float* __restrict__ ar,
    const float* __restrict__ b, float* __restrict__ br,
    const float* __restrict__ c, float* __restrict__ cr)
{
    int i = blockIdx.x * 256 + threadIdx.x;
    const float* src; float* dst; int idx;
    if (i < XR_N4)                 { src = a; dst = ar; idx = i; }
    else if (i < XR_N4 + WAR_N4)   { src = b; dst = br; idx = i - XR_N4; }
    else if (i < ROUND_TOTAL4)     { src = c; dst = cr; idx = i - XR_N4 - WAR_N4; }
    else return;
    float4 v = *(const float4*)(src + (size_t)idx * 4);
    float4 w;
    w.x = tf32v(v.x); w.y = tf32v(v.y); w.z = tf32v(v.z); w.w = tf32v(v.w);
    *(float4*)(dst + (size_t)idx * 4) = w;
}

// ===========================================================================
// tf32 mma.sync GEMM (R12-proven): C = A @ B + bias, B row-major.
// CTA tile 64x128, 128 threads (4 warps 2x2), warp tile 32x64.
// 2-stage cp.async double buffer. 4 CTAs/SM via 128-reg cap.
// ===========================================================================
#define LDA 36
#define LDB 136
#define A_STAGE (64 * LDA)      // floats
#define B_STAGE (32 * LDB)
#define GEMM_SMEM ((2 * (A_STAGE + B_STAGE)) * 4)

__global__ __launch_bounds__(128, 4)
void gemm_tf32(const float* __restrict__ A, const float* __restrict__ B,
               const float* __restrict__ bias, float* __restrict__ C,
               int M, int N, int K, int round_out)
{
    extern __shared__ float smem[];
    float* As = smem;                      // [2][A_STAGE]
    float* Bs = smem + 2 * A_STAGE;        // [2][B_STAGE]
    const uint32_t as_u32 = smem_u32(As);
    const uint32_t bs_u32 = smem_u32(Bs);

    const int tid  = threadIdx.x;
    const int wid  = tid >> 5;
    const int lane = tid & 31;
    const int g = lane >> 2;
    const int t = lane & 3;
    const int wy = wid >> 1;                // 0..1 (M)
    const int wx = wid & 1;                 // 0..1 (N)
    const int row0 = blockIdx.y * 64;
    const int col0 = blockIdx.x * 128;
    const int NS = K >> 5;

    const float* Ag = A + (size_t)row0 * K;
    const float* Bg = B + col0;

    auto copy_stage = [&](int s, int buf) {
        const int k0 = s * 32;
        // A: 64 rows x 8 float4 = 512 -> 4 per thread
#pragma unroll
        for (int u = 0; u < 4; u++) {
            int idx = u * 128 + tid;
            int row = idx >> 3;
            int c4  = idx & 7;
            CP_ASYNC16(as_u32 + (buf * A_STAGE + row * LDA + c4 * 4) * 4,
                       Ag + (size_t)row * K + k0 + c4 * 4);
        }
        // B: 32 rows x 32 float4 = 1024 -> 8 per thread
#pragma unroll
        for (int u = 0; u < 8; u++) {
            int idx = u * 128 + tid;
            int row = idx >> 5;
            int c4  = idx & 31;
            CP_ASYNC16(bs_u32 + (buf * B_STAGE + row * LDB + c4 * 4) * 4,
                       Bg + (size_t)(k0 + row) * N + c4 * 4);
        }
    };

    float acc[2][8][4];
#pragma unroll
    for (int mt = 0; mt < 2; mt++)
#pragma unroll
        for (int nt = 0; nt < 8; nt++)
#pragma unroll
            for (int r = 0; r < 4; r++) acc[mt][nt][r] = 0.f;

    copy_stage(0, 0);
    CP_COMMIT();

    for (int s = 0; s < NS; s++) {
        const int buf = s & 1;
        if (s + 1 < NS) {
            copy_stage(s + 1, buf ^ 1);
            CP_COMMIT();
            CP_WAIT1();
        } else {
            CP_WAIT0();
        }
        __syncthreads();

        const float* Ab = As + buf * A_STAGE;
        const float* Bb = Bs + buf * B_STAGE;

#pragma unroll
        for (int ks = 0; ks < 4; ks++) {
            const int kk = ks * 8;
            uint32_t af[2][4];
#pragma unroll
            for (int mt = 0; mt < 2; mt++) {
                const float* pa = Ab + (wy * 32 + mt * 16 + g) * LDA + kk + t;
                af[mt][0] = __float_as_uint(pa[0]);
                af[mt][1] = __float_as_uint(pa[8 * LDA]);
                af[mt][2] = __float_as_uint(pa[4]);
                af[mt][3] = __float_as_uint(pa[8 * LDA + 4]);
            }
            uint32_t bf[8][2];
#pragma unroll
            for (int nt = 0; nt < 8; nt++) {
                const float* pb = Bb + (kk + t) * LDB + wx * 64 + nt * 8 + g;
                bf[nt][0] = __float_as_uint(pb[0]);
                bf[nt][1] = __float_as_uint(pb[4 * LDB]);
            }
#pragma unroll
            for (int mt = 0; mt < 2; mt++)
#pragma unroll
                for (int nt = 0; nt < 8; nt++)
                    mma_tf32(acc[mt][nt], af[mt][0], af[mt][1], af[mt][2], af[mt][3],
                             bf[nt][0], bf[nt][1]);
        }
        __syncthreads();
    }

#pragma unroll
    for (int mt = 0; mt < 2; mt++) {
        int m = row0 + wy * 32 + mt * 16 + g;
#pragma unroll
        for (int nt = 0; nt < 8; nt++) {
            int n = col0 + wx * 64 + nt * 8 + 2 * t;
            float2 o0, o1;
            o0.x = acc[mt][nt][0] + bias[n];
            o0.y = acc[mt][nt][1] + bias[n + 1];
            o1.x = acc[mt][nt][2] + bias[n];
            o1.y = acc[mt][nt][3] + bias[n + 1];
            if (round_out) {
                o0.x = tf32v(o0.x); o0.y = tf32v(o0.y);
                o1.x = tf32v(o1.x); o1.y = tf32v(o1.y);
            }
            *(float2*)(C + (size_t)m * N + n)       = o0;
            *(float2*)(C + (size_t)(m + 8) * N + n) = o1;
        }
    }
}

// ===========================================================================
// Flash attention, tf32 mma.sync (R12-proven structure).
// CTA = (head, 64 q rows), 4 warps. Q persistent fragments, shfl-transposed
// P (no P smem round-trip), cp.async K/V loads.
// NEW: __launch_bounds__(128, 3) — cap regs at 170 to GUARANTEE 3 CTAs/SM
// (smem 70KB x 3 = 210KB <= 228KB). Cross-CTA overlap hides K/V latency.
// ===========================================================================
#define ALD 68                       // K lead dim (S-phase B reads: bank 4g+t)
#define VLD 72                       // V lead dim (PV B reads: bank 8t+g)
#define KP_FLOATS (128 * ALD)        // K tile (also Q staging area before loop)
#define AT_V  KP_FLOATS
#define ATTN_FLOATS (KP_FLOATS + 128 * VLD)
#define ATTN_BYTES  (ATTN_FLOATS * 4)

__global__ __launch_bounds__(128, 3)
void attn_mma(const float* __restrict__ qkv, float* __restrict__ out)
{
    extern __shared__ float sm[];
    float* KPs = sm;               // K tile (Q staged here once before loop)
    float* Vs  = sm + AT_V;
    const uint32_t kp_u32 = smem_u32(KPs);
    const uint32_t vs_u32 = smem_u32(Vs);

    const int tid  = threadIdx.x;
    const int lane = tid & 31;
    const int wid  = tid >> 5;     // 0..3
    const int g = lane >> 2;
    const int t = lane & 3;
    const int h  = blockIdx.y;
    const int qb = (int)gridDim.x - 1 - (int)blockIdx.x;   // heavy CTAs first
    const int q0 = qb * 64;
    const int rowbase = wid * 16;
    const int nkb = (qb >> 1) + 1;

    // ---- stage Q into KPs (x0.125 exponent-only: stays valid tf32) ----
#pragma unroll
    for (int u = 0; u < 8; u++) {
        int i4 = u * 128 + tid;
        int r = i4 >> 4;
        int d = (i4 & 15) * 4;
        float4 v = *(const float4*)(qkv + (size_t)(q0 + r) * QKVN + h * HD + d);
        v.x *= 0.125f; v.y *= 0.125f; v.z *= 0.125f; v.w *= 0.125f;
        *(float4*)&KPs[r * ALD + d] = v;
    }
    __syncthreads();

    uint32_t qf[8][4];
#pragma unroll
    for (int ks = 0; ks < 8; ks++) {
        const float* pa = KPs + (rowbase + g) * ALD + ks * 8 + t;
        qf[ks][0] = __float_as_uint(pa[0]);
        qf[ks][1] = __float_as_uint(pa[8 * ALD]);
        qf[ks][2] = __float_as_uint(pa[4]);
        qf[ks][3] = __float_as_uint(pa[8 * ALD + 4]);
    }

    float O[8][4];
    float m0 = -1e30f, m1 = -1e30f, l0 = 0.f, l1 = 0.f;
#pragma unroll
    for (int nt = 0; nt < 8; nt++)
#pragma unroll
        for (int r = 0; r < 4; r++) O[nt][r] = 0.f;

    for (int kb = 0; kb < nkb; kb++) {
        __syncthreads();   // prior consumers of KPs/Vs done (incl. qf reads @kb=0)

        // ---- async copy K -> KPs, V -> Vs (values already tf32) ----
#pragma unroll
        for (int u = 0; u < 16; u++) {
            int i4 = u * 128 + tid;
            int r = i4 >> 4;
            int d = (i4 & 15) * 4;
            const float* base = qkv + (size_t)(kb * 128 + r) * QKVN + h * HD;
            CP_ASYNC16(kp_u32 + (r * ALD + d) * 4, base + HID + d);
            CP_ASYNC16(vs_u32 + (r * VLD + d) * 4, base + 2 * HID + d);
        }
        CP_COMMIT();
        CP_WAIT0();
        __syncthreads();

        // ---- S = Q @ K^T ----
        float S[16][4];
#pragma unroll
        for (int nt = 0; nt < 16; nt++)
#pragma unroll
            for (int r = 0; r < 4; r++) S[nt][r] = 0.f;

#pragma unroll
        for (int ks = 0; ks < 8; ks++) {
#pragma unroll
            for (int nt = 0; nt < 16; nt++) {
                const float* pb = KPs + (nt * 8 + g) * ALD + ks * 8 + t;
                uint32_t b0 = __float_as_uint(pb[0]);
                uint32_t b1 = __float_as_uint(pb[4]);
                mma_tf32(S[nt], qf[ks][0], qf[ks][1], qf[ks][2], qf[ks][3], b0, b1);
            }
        }

        // ---- causal mask (last k-block only) ----
        if (kb == nkb - 1) {
            const int r0 = q0 + rowbase + g, r1 = r0 + 8;
            const int cb = kb * 128;
#pragma unroll
            for (int nt = 0; nt < 16; nt++) {
                int c = cb + nt * 8 + 2 * t;
                if (c     > r0) S[nt][0] = -1e30f;
                if (c + 1 > r0) S[nt][1] = -1e30f;
                if (c     > r1) S[nt][2] = -1e30f;
                if (c + 1 > r1) S[nt][3] = -1e30f;
            }
        }

        // ---- online softmax ----
        float mt0 = -1e30f, mt1 = -1e30f;
#pragma unroll
        for (int nt = 0; nt < 16; nt++) {
            mt0 = fmaxf(mt0, fmaxf(S[nt][0], S[nt][1]));
            mt1 = fmaxf(mt1, fmaxf(S[nt][2], S[nt][3]));
        }
        mt0 = fmaxf(mt0, __shfl_xor_sync(0xffffffffu, mt0, 1));
        mt0 = fmaxf(mt0, __shfl_xor_sync(0xffffffffu, mt0, 2));
        mt1 = fmaxf(mt1, __shfl_xor_sync(0xffffffffu, mt1, 1));
        mt1 = fmaxf(mt1, __shfl_xor_sync(0xffffffffu, mt1, 2));
        float mn0 = fmaxf(m0, mt0), mn1 = fmaxf(m1, mt1);
        float al0 = __expf(m0 - mn0), al1 = __expf(m1 - mn1);
        float ps0 = 0.f, ps1 = 0.f;
#pragma unroll
        for (int nt = 0; nt < 16; nt++) {
            float p00 = __expf(S[nt][0] - mn0);
            float p01 = __expf(S[nt][1] - mn0);
            float p10 = __expf(S[nt][2] - mn1);
            float p11 = __expf(S[nt][3] - mn1);
            S[nt][0] = p00; S[nt][1] = p01; S[nt][2] = p10; S[nt][3] = p11;
            ps0 += p00 + p01;
            ps1 += p10 + p11;
        }
        ps0 += __shfl_xor_sync(0xffffffffu, ps0, 1);
        ps0 += __shfl_xor_sync(0xffffffffu, ps0, 2);
        ps1 += __shfl_xor_sync(0xffffffffu, ps1, 1);
        ps1 += __shfl_xor_sync(0xffffffffu, ps1, 2);
        l0 = l0 * al0 + ps0;  m0 = mn0;
        l1 = l1 * al1 + ps1;  m1 = mn1;
#pragma unroll
        for (int nt = 0; nt < 8; nt++) {
            O[nt][0] *= al0; O[nt][1] *= al0;
            O[nt][2] *= al1; O[nt][3] *= al1;
        }

        // ---- O += P @ V : A-frag via shfl transpose of S (no smem, no sync) ----
        {
            const int src0 = (lane & 28) | (t >> 1);
            const int src1 = src0 | 2;
            const bool odd = (t & 1);
#pragma unroll
            for (int ks = 0; ks < 16; ks++) {
                float p0 = tf32v(S[ks][0]), p1 = tf32v(S[ks][1]);
                float p2 = tf32v(S[ks][2]), p3 = tf32v(S[ks][3]);
                float v00 = __shfl_sync(0xffffffffu, p0, src0);
                float v01 = __shfl_sync(0xffffffffu, p1, src0);
                float v02 = __shfl_sync(0xffffffffu, p2, src0);
                float v03 = __shfl_sync(0xffffffffu, p3, src0);
                float v10 = __shfl_sync(0xffffffffu, p0, src1);
                float v11 = __shfl_sync(0xffffffffu, p1, src1);
                float v12 = __shfl_sync(0xffffffffu, p2, src1);
                float v13 = __shfl_sync(0xffffffffu, p3, src1);
                uint32_t a0 = __float_as_uint(odd ? v01 : v00);
                uint32_t a1 = __float_as_uint(odd ? v03 : v02);
                uint32_t a2 = __float_as_uint(odd ? v11 : v10);
                uint32_t a3 = __float_as_uint(odd ? v13 : v12);
#pragma unroll
                for (int nt = 0; nt < 8; nt++) {
                    uint32_t b0 = __float_as_uint(Vs[(ks * 8 + t)     * VLD + nt * 8 + g]);
                    uint32_t b1 = __float_as_uint(Vs[(ks * 8 + t + 4) * VLD + nt * 8 + g]);
                    mma_tf32(O[nt], a0, a1, a2, a3, b0, b1);
                }
            }
        }
    }

    // ---- epilogue: normalize, round to tf32 (feeds proj GEMM) ----
    float inv0 = 1.0f / l0, inv1 = 1.0f / l1;
#pragma unroll
    for (int nt = 0; nt < 8; nt++) {
        int c = h * HD + nt * 8 + 2 * t;
        float2 o0, o1;
        o0.x = tf32v(O[nt][0] * inv0); o0.y = tf32v(O[nt][1] * inv0);
        o1.x = tf32v(O[nt][2] * inv1); o1.y = tf32v(O[nt][3] * inv1);
        *(float2*)(out + (size_t)(q0 + rowbase + g)     * HID + c) = o0;
        *(float2*)(out + (size_t)(q0 + rowbase + g + 8) * HID + c) = o1;
    }
}

// ---------------------------------------------------------------------------
// Launch
// ---------------------------------------------------------------------------
extern "C" void kernel_launch(void* const* d_in, const int* in_sizes, int n_in,
                              void* d_out, int out_size)
{
    const float* x      = (const float*)d_in[0];
    const float* w_attn = (const float*)d_in[1];
    const float* b_attn = (const float*)d_in[2];
    const float* w_proj = (const float*)d_in[3];
    const float* b_proj = (const float*)d_in[4];
    float* out = (float*)d_out;

    float *qkv_p, *attn_p, *xr_p, *war_p, *wpr_p;
    cudaGetSymbolAddress((void**)&qkv_p,  g_qkv);
    cudaGetSymbolAddress((void**)&attn_p, g_attn);
    cudaGetSymbolAddress((void**)&xr_p,   g_xr);
    cudaGetSymbolAddress((void**)&war_p,  g_war);
    cudaGetSymbolAddress((void**)&wpr_p,  g_wpr);

    cudaFuncSetAttribute(attn_mma,
                         cudaFuncAttributeMaxDynamicSharedMemorySize, ATTN_BYTES);
    cudaFuncSetAttribute(gemm_tf32,
                         cudaFuncAttributeMaxDynamicSharedMemorySize, GEMM_SMEM);

    // 0) pre-round inputs to tf32 (single fused launch)
    round3_tf32<<<(ROUND_TOTAL4 + 255) / 256, 256>>>(
        x, xr_p, w_attn, war_p, w_proj, wpr_p);

    // 1) QKV = Xr @ W_attn_r + b_attn     [2048, 3072]  (epilogue rounds to tf32)
    gemm_tf32<<<dim3(QKVN / 128, SEQ / 64), 128, GEMM_SMEM>>>(
        xr_p, war_p, b_attn, qkv_p, SEQ, QKVN, HID, 1);

    // 2) causal flash attention -> g_attn [2048, 1024]  (epilogue rounds to tf32)
    attn_mma<<<dim3(SEQ / 64, NH), 128, ATTN_BYTES>>>(qkv_p, attn_p);

    // 3) out = attn @ W_proj_r + b_proj   [2048, 1024]
    gemm_tf32<<<dim3(HID / 128, SEQ / 64), 128, GEMM_SMEM>>>(
        attn_p, wpr_p, b_proj, out, SEQ, HID, HID, 0);
}

// round 16
// speedup vs baseline: 1.0310x; 1.0213x over previous
#include <cuda_runtime.h>
#include <cuda_bf16.h>
#include <cstdint>

// Problem constants
#define SEQ  2048
#define HID  1024
#define NH   16
#define HD   64
#define QKVN (3 * HID)   // 3072

// Scratch (allocation-free rule: __device__ globals)
__device__ float g_qkv[SEQ * QKVN];        // [2048, 3072]  (tf32-rounded values)
__device__ float g_attn[SEQ * HID];        // [2048, 1024]  (tf32-rounded values)
__device__ float g_xr[SEQ * HID];          // x rounded to tf32
__device__ float g_war[HID * QKVN];        // w_attn rounded to tf32
__device__ float g_wpr[HID * HID];         // w_proj rounded to tf32
__device__ float g_pp[2 * SEQ * HID];      // proj split-K partials

// ===========================================================================
// Helpers
// ===========================================================================
__device__ __forceinline__ uint32_t smem_u32(const void* p) {
    uint32_t a;
    asm("{ .reg .u64 t; cvta.to.shared.u64 t, %1; cvt.u32.u64 %0, t; }" : "=r"(a) : "l"(p));
    return a;
}
__device__ __forceinline__ uint32_t f2tf32(float v) {
    uint32_t r;
    asm("cvt.rna.tf32.f32 %0, %1;" : "=r"(r) : "f"(v));
    return r;
}
__device__ __forceinline__ float tf32v(float v) {
    return __uint_as_float(f2tf32(v));
}
__device__ __forceinline__ void mma_tf32(float d[4],
                                         uint32_t a0, uint32_t a1, uint32_t a2, uint32_t a3,
                                         uint32_t b0, uint32_t b1) {
    asm volatile(
        "mma.sync.aligned.m16n8k8.row.col.f32.tf32.tf32.f32 "
        "{%0,%1,%2,%3}, {%4,%5,%6,%7}, {%8,%9}, {%0,%1,%2,%3};"
        : "+f"(d[0]), "+f"(d[1]), "+f"(d[2]), "+f"(d[3])
        : "r"(a0), "r"(a1), "r"(a2), "r"(a3), "r"(b0), "r"(b1));
}
#define CP_ASYNC16(dst_u32, src_ptr) \
    asm volatile("cp.async.cg.shared.global [%0], [%1], 16;" :: "r"(dst_u32), "l"(src_ptr))
#define CP_COMMIT() asm volatile("cp.async.commit_group;" ::: "memory")
#define CP_WAIT1()  asm volatile("cp.async.wait_group 1;" ::: "memory")
#define CP_WAIT0()  asm volatile("cp.async.wait_group 0;" ::: "memory")

// ===========================================================================
// Fused elementwise tf32 rounding for x / w_attn / w_proj (one launch)
// ===========================================================================
#define XR_N4  (SEQ * HID / 4)
#define WAR_N4 (HID * QKVN / 4)
#define WPR_N4 (HID * HID / 4)
#define ROUND_TOTAL4 (XR_N4 + WAR_N4 + WPR_N4)

__global__ __launch_bounds__(256) void round3_tf32(
    const float* __restrict__ a, float* __restrict__ ar,
    const float* __restrict__ b, float* __restrict__ br,
    const float* __restrict__ c, float* __restrict__ cr)
{
    int i = blockIdx.x * 256 + threadIdx.x;
    const float* src; float* dst; int idx;
    if (i < XR_N4)                 { src = a; dst = ar; idx = i; }
    else if (i < XR_N4 + WAR_N4)   { src = b; dst = br; idx = i - XR_N4; }
    else if (i < ROUND_TOTAL4)     { src = c; dst = cr; idx = i - XR_N4 - WAR_N4; }
    else return;
    float4 v = *(const float4*)(src + (size_t)idx * 4);
    float4 w;
    w.x = tf32v(v.x); w.y = tf32v(v.y); w.z = tf32v(v.z); w.w = tf32v(v.w);
    *(float4*)(dst + (size_t)idx * 4) = w;
}

// ===========================================================================
// Split-K fixup: out = p0 + p1 + bias     [SEQ, HID]
// ===========================================================================
__global__ __launch_bounds__(256) void fixup_proj(
    const float* __restrict__ pp, const float* __restrict__ bias,
    float* __restrict__ out)
{
    int i = blockIdx.x * 256 + threadIdx.x;          // float4 index
    if (i >= SEQ * HID / 4) return;
    int col = (i * 4) & (HID - 1);
    float4 p0 = *(const float4*)(pp + (size_t)i * 4);
    float4 p1 = *(const float4*)(pp + (size_t)SEQ * HID + (size_t)i * 4);
    float4 bb = *(const float4*)(bias + col);
    float4 o;
    o.x = p0.x + p1.x + bb.x;
    o.y = p0.y + p1.y + bb.y;
    o.z = p0.z + p1.z + bb.z;
    o.w = p0.w + p1.w + bb.w;
    *(float4*)(out + (size_t)i * 4) = o;
}

// ===========================================================================
// tf32 mma.sync GEMM (R12-proven core): C = A @ B (+ bias), B row-major.
// CTA tile 64x128, 128 threads (4 warps 2x2), warp tile 32x64.
// 2-stage cp.async double buffer. 4 CTAs/SM via 128-reg cap.
// mode 0: +bias, write            (final output)
// mode 1: +bias, tf32-round, write (feeds next tensor stage)
// mode 2: raw partial to C + z*M*N, K-slice = [z*KS, (z+1)*KS)  (split-K)
// ===========================================================================
#define LDA 36
#define LDB 136
#define A_STAGE (64 * LDA)      // floats
#define B_STAGE (32 * LDB)
#define GEMM_SMEM ((2 * (A_STAGE + B_STAGE)) * 4)

__global__ __launch_bounds__(128, 4)
void gemm_tf32(const float* __restrict__ A, const float* __restrict__ B,
               const float* __restrict__ bias, float* __restrict__ C,
               int M, int N, int K, int KS, int mode)
{
    extern __shared__ float smem[];
    float* As = smem;                      // [2][A_STAGE]
    float* Bs = smem + 2 * A_STAGE;        // [2][B_STAGE]
    const uint32_t as_u32 = smem_u32(As);
    const uint32_t bs_u32 = smem_u32(Bs);

    const int tid  = threadIdx.x;
    const int wid  = tid >> 5;
    const int lane = tid & 31;
    const int g = lane >> 2;
    const int t = lane & 3;
    const int wy = wid >> 1;                // 0..1 (M)
    const int wx = wid & 1;                 // 0..1 (N)
    const int row0 = blockIdx.y * 64;
    const int col0 = blockIdx.x * 128;
    const int k0   = blockIdx.z * KS;
    const int NS = KS >> 5;

    const float* Ag = A + (size_t)row0 * K + k0;
    const float* Bg = B + (size_t)k0 * N + col0;

    auto copy_stage = [&](int s, int buf) {
        const int kk0 = s * 32;
        // A: 64 rows x 8 float4 = 512 -> 4 per thread
#pragma unroll
        for (int u = 0; u < 4; u++) {
            int idx = u * 128 + tid;
            int row = idx >> 3;
            int c4  = idx & 7;
            CP_ASYNC16(as_u32 + (buf * A_STAGE + row * LDA + c4 * 4) * 4,
                       Ag + (size_t)row * K + kk0 + c4 * 4);
        }
        // B: 32 rows x 32 float4 = 1024 -> 8 per thread
#pragma unroll
        for (int u = 0; u < 8; u++) {
            int idx = u * 128 + tid;
            int row = idx >> 5;
            int c4  = idx & 31;
            CP_ASYNC16(bs_u32 + (buf * B_STAGE + row * LDB + c4 * 4) * 4,
                       Bg + (size_t)(kk0 + row) * N + c4 * 4);
        }
    };

    float acc[2][8][4];
#pragma unroll
    for (int mt = 0; mt < 2; mt++)
#pragma unroll
        for (int nt = 0; nt < 8; nt++)
#pragma unroll
            for (int r = 0; r < 4; r++) acc[mt][nt][r] = 0.f;

    copy_stage(0, 0);
    CP_COMMIT();

    for (int s = 0; s < NS; s++) {
        const int buf = s & 1;
        if (s + 1 < NS) {
            copy_stage(s + 1, buf ^ 1);
            CP_COMMIT();
            CP_WAIT1();
        } else {
            CP_WAIT0();
        }
        __syncthreads();

        const float* Ab = As + buf * A_STAGE;
        const float* Bb = Bs + buf * B_STAGE;

#pragma unroll
        for (int ks = 0; ks < 4; ks++) {
            const int kk = ks * 8;
            uint32_t af[2][4];
#pragma unroll
            for (int mt = 0; mt < 2; mt++) {
                const float* pa = Ab + (wy * 32 + mt * 16 + g) * LDA + kk + t;
                af[mt][0] = __float_as_uint(pa[0]);
                af[mt][1] = __float_as_uint(pa[8 * LDA]);
                af[mt][2] = __float_as_uint(pa[4]);
                af[mt][3] = __float_as_uint(pa[8 * LDA + 4]);
            }
            uint32_t bf[8][2];
#pragma unroll
            for (int nt = 0; nt < 8; nt++) {
                const float* pb = Bb + (kk + t) * LDB + wx * 64 + nt * 8 + g;
                bf[nt][0] = __float_as_uint(pb[0]);
                bf[nt][1] = __float_as_uint(pb[4 * LDB]);
            }
#pragma unroll
            for (int mt = 0; mt < 2; mt++)
#pragma unroll
                for (int nt = 0; nt < 8; nt++)
                    mma_tf32(acc[mt][nt], af[mt][0], af[mt][1], af[mt][2], af[mt][3],
                             bf[nt][0], bf[nt][1]);
        }
        __syncthreads();
    }

    float* Cw = (mode == 2) ? (C + (size_t)blockIdx.z * M * N) : C;

#pragma unroll
    for (int mt = 0; mt < 2; mt++) {
        int m = row0 + wy * 32 + mt * 16 + g;
#pragma unroll
        for (int nt = 0; nt < 8; nt++) {
            int n = col0 + wx * 64 + nt * 8 + 2 * t;
            float2 o0, o1;
            if (mode == 2) {
                o0.x = acc[mt][nt][0]; o0.y = acc[mt][nt][1];
                o1.x = acc[mt][nt][2]; o1.y = acc[mt][nt][3];
            } else {
                o0.x = acc[mt][nt][0] + bias[n];
                o0.y = acc[mt][nt][1] + bias[n + 1];
                o1.x = acc[mt][nt][2] + bias[n];
                o1.y = acc[mt][nt][3] + bias[n + 1];
                if (mode == 1) {
                    o0.x = tf32v(o0.x); o0.y = tf32v(o0.y);
                    o1.x = tf32v(o1.x); o1.y = tf32v(o1.y);
                }
            }
            *(float2*)(Cw + (size_t)m * N + n)       = o0;
            *(float2*)(Cw + (size_t)(m + 8) * N + n) = o1;
        }
    }
}

// ===========================================================================
// Flash attention, tf32 mma.sync (EXACT R12 kernel — no launch-bounds cap).
// CTA = (head, 64 q rows), 4 warps. Q persistent fragments, shfl-transposed
// P (no P smem round-trip), cp.async K/V loads.
// ===========================================================================
#define ALD 68                       // K lead dim (S-phase B reads: bank 4g+t)
#define VLD 72                       // V lead dim (PV B reads: bank 8t+g)
#define KP_FLOATS (128 * ALD)        // K tile (also Q staging area before loop)
#define AT_V  KP_FLOATS
#define ATTN_FLOATS (KP_FLOATS + 128 * VLD)
#define ATTN_BYTES  (ATTN_FLOATS * 4)

__global__ __launch_bounds__(128)
void attn_mma(const float* __restrict__ qkv, float* __restrict__ out)
{
    extern __shared__ float sm[];
    float* KPs = sm;               // K tile (Q staged here once before loop)
    float* Vs  = sm + AT_V;
    const uint32_t kp_u32 = smem_u32(KPs);
    const uint32_t vs_u32 = smem_u32(Vs);

    const int tid  = threadIdx.x;
    const int lane = tid & 31;
    const int wid  = tid >> 5;     // 0..3
    const int g = lane >> 2;
    const int t = lane & 3;
    const int h  = blockIdx.y;
    const int qb = (int)gridDim.x - 1 - (int)blockIdx.x;   // heavy CTAs first
    const int q0 = qb * 64;
    const int rowbase = wid * 16;
    const int nkb = (qb >> 1) + 1;

    // ---- stage Q into KPs (x0.125 exponent-only: stays valid tf32) ----
#pragma unroll
    for (int u = 0; u < 8; u++) {
        int i4 = u * 128 + tid;
        int r = i4 >> 4;
        int d = (i4 & 15) * 4;
        float4 v = *(const float4*)(qkv + (size_t)(q0 + r) * QKVN + h * HD + d);
        v.x *= 0.125f; v.y *= 0.125f; v.z *= 0.125f; v.w *= 0.125f;
        *(float4*)&KPs[r * ALD + d] = v;
    }
    __syncthreads();

    uint32_t qf[8][4];
#pragma unroll
    for (int ks = 0; ks < 8; ks++) {
        const float* pa = KPs + (rowbase + g) * ALD + ks * 8 + t;
        qf[ks][0] = __float_as_uint(pa[0]);
        qf[ks][1] = __float_as_uint(pa[8 * ALD]);
        qf[ks][2] = __float_as_uint(pa[4]);
        qf[ks][3] = __float_as_uint(pa[8 * ALD + 4]);
    }

    float O[8][4];
    float m0 = -1e30f, m1 = -1e30f, l0 = 0.f, l1 = 0.f;
#pragma unroll
    for (int nt = 0; nt < 8; nt++)
#pragma unroll
        for (int r = 0; r < 4; r++) O[nt][r] = 0.f;

    for (int kb = 0; kb < nkb; kb++) {
        __syncthreads();   // prior consumers of KPs/Vs done (incl. qf reads @kb=0)

        // ---- async copy K -> KPs, V -> Vs (values already tf32) ----
#pragma unroll
        for (int u = 0; u < 16; u++) {
            int i4 = u * 128 + tid;
            int r = i4 >> 4;
            int d = (i4 & 15) * 4;
            const float* base = qkv + (size_t)(kb * 128 + r) * QKVN + h * HD;
            CP_ASYNC16(kp_u32 + (r * ALD + d) * 4, base + HID + d);
            CP_ASYNC16(vs_u32 + (r * VLD + d) * 4, base + 2 * HID + d);
        }
        CP_COMMIT();
        CP_WAIT0();
        __syncthreads();

        // ---- S = Q @ K^T ----
        float S[16][4];
#pragma unroll
        for (int nt = 0; nt < 16; nt++)
#pragma unroll
            for (int r = 0; r < 4; r++) S[nt][r] = 0.f;

#pragma unroll
        for (int ks = 0; ks < 8; ks++) {
#pragma unroll
            for (int nt = 0; nt < 16; nt++) {
                const float* pb = KPs + (nt * 8 + g) * ALD + ks * 8 + t;
                uint32_t b0 = __float_as_uint(pb[0]);
                uint32_t b1 = __float_as_uint(pb[4]);
                mma_tf32(S[nt], qf[ks][0], qf[ks][1], qf[ks][2], qf[ks][3], b0, b1);
            }
        }

        // ---- causal mask (last k-block only) ----
        if (kb == nkb - 1) {
            const int r0 = q0 + rowbase + g, r1 = r0 + 8;
            const int cb = kb * 128;
#pragma unroll
            for (int nt = 0; nt < 16; nt++) {
                int c = cb + nt * 8 + 2 * t;
                if (c     > r0) S[nt][0] = -1e30f;
                if (c + 1 > r0) S[nt][1] = -1e30f;
                if (c     > r1) S[nt][2] = -1e30f;
                if (c + 1 > r1) S[nt][3] = -1e30f;
            }
        }

        // ---- online softmax ----
        float mt0 = -1e30f, mt1 = -1e30f;
#pragma unroll
        for (int nt = 0; nt < 16; nt++) {
            mt0 = fmaxf(mt0, fmaxf(S[nt][0], S[nt][1]));
            mt1 = fmaxf(mt1, fmaxf(S[nt][2], S[nt][3]));
        }
        mt0 = fmaxf(mt0, __shfl_xor_sync(0xffffffffu, mt0, 1));
        mt0 = fmaxf(mt0, __shfl_xor_sync(0xffffffffu, mt0, 2));
        mt1 = fmaxf(mt1, __shfl_xor_sync(0xffffffffu, mt1, 1));
        mt1 = fmaxf(mt1, __shfl_xor_sync(0xffffffffu, mt1, 2));
        float mn0 = fmaxf(m0, mt0), mn1 = fmaxf(m1, mt1);
        float al0 = __expf(m0 - mn0), al1 = __expf(m1 - mn1);
        float ps0 = 0.f, ps1 = 0.f;
#pragma unroll
        for (int nt = 0; nt < 16; nt++) {
            float p00 = __expf(S[nt][0] - mn0);
            float p01 = __expf(S[nt][1] - mn0);
            float p10 = __expf(S[nt][2] - mn1);
            float p11 = __expf(S[nt][3] - mn1);
            S[nt][0] = p00; S[nt][1] = p01; S[nt][2] = p10; S[nt][3] = p11;
            ps0 += p00 + p01;
            ps1 += p10 + p11;
        }
        ps0 += __shfl_xor_sync(0xffffffffu, ps0, 1);
        ps0 += __shfl_xor_sync(0xffffffffu, ps0, 2);
        ps1 += __shfl_xor_sync(0xffffffffu, ps1, 1);
        ps1 += __shfl_xor_sync(0xffffffffu, ps1, 2);
        l0 = l0 * al0 + ps0;  m0 = mn0;
        l1 = l1 * al1 + ps1;  m1 = mn1;
#pragma unroll
        for (int nt = 0; nt < 8; nt++) {
            O[nt][0] *= al0; O[nt][1] *= al0;
            O[nt][2] *= al1; O[nt][3] *= al1;
        }

        // ---- O += P @ V : A-frag via shfl transpose of S (no smem, no sync) ----
        {
            const int src0 = (lane & 28) | (t >> 1);
            const int src1 = src0 | 2;
            const bool odd = (t & 1);
#pragma unroll
            for (int ks = 0; ks < 16; ks++) {
                float p0 = tf32v(S[ks][0]), p1 = tf32v(S[ks][1]);
                float p2 = tf32v(S[ks][2]), p3 = tf32v(S[ks][3]);
                float v00 = __shfl_sync(0xffffffffu, p0, src0);
                float v01 = __shfl_sync(0xffffffffu, p1, src0);
                float v02 = __shfl_sync(0xffffffffu, p2, src0);
                float v03 = __shfl_sync(0xffffffffu, p3, src0);
                float v10 = __shfl_sync(0xffffffffu, p0, src1);
                float v11 = __shfl_sync(0xffffffffu, p1, src1);
                float v12 = __shfl_sync(0xffffffffu, p2, src1);
                float v13 = __shfl_sync(0xffffffffu, p3, src1);
                uint32_t a0 = __float_as_uint(odd ? v01 : v00);
                uint32_t a1 = __float_as_uint(odd ? v03 : v02);
                uint32_t a2 = __float_as_uint(odd ? v11 : v10);
                uint32_t a3 = __float_as_uint(odd ? v13 : v12);
#pragma unroll
                for (int nt = 0; nt < 8; nt++) {
                    uint32_t b0 = __float_as_uint(Vs[(ks * 8 + t)     * VLD + nt * 8 + g]);
                    uint32_t b1 = __float_as_uint(Vs[(ks * 8 + t + 4) * VLD + nt * 8 + g]);
                    mma_tf32(O[nt], a0, a1, a2, a3, b0, b1);
                }
            }
        }
    }

    // ---- epilogue: normalize, round to tf32 (feeds proj GEMM) ----
    float inv0 = 1.0f / l0, inv1 = 1.0f / l1;
#pragma unroll
    for (int nt = 0; nt < 8; nt++) {
        int c = h * HD + nt * 8 + 2 * t;
        float2 o0, o1;
        o0.x = tf32v(O[nt][0] * inv0); o0.y = tf32v(O[nt][1] * inv0);
        o1.x = tf32v(O[nt][2] * inv1); o1.y = tf32v(O[nt][3] * inv1);
        *(float2*)(out + (size_t)(q0 + rowbase + g)     * HID + c) = o0;
        *(float2*)(out + (size_t)(q0 + rowbase + g + 8) * HID + c) = o1;
    }
}

// ---------------------------------------------------------------------------
// Launch
// ---------------------------------------------------------------------------
extern "C" void kernel_launch(void* const* d_in, const int* in_sizes, int n_in,
                              void* d_out, int out_size)
{
    const float* x      = (const float*)d_in[0];
    const float* w_attn = (const float*)d_in[1];
    const float* b_attn = (const float*)d_in[2];
    const float* w_proj = (const float*)d_in[3];
    const float* b_proj = (const float*)d_in[4];
    float* out = (float*)d_out;

    float *qkv_p, *attn_p, *xr_p, *war_p, *wpr_p, *pp_p;
    cudaGetSymbolAddress((void**)&qkv_p,  g_qkv);
    cudaGetSymbolAddress((void**)&attn_p, g_attn);
    cudaGetSymbolAddress((void**)&xr_p,   g_xr);
    cudaGetSymbolAddress((void**)&war_p,  g_war);
    cudaGetSymbolAddress((void**)&wpr_p,  g_wpr);
    cudaGetSymbolAddress((void**)&pp_p,   g_pp);

    cudaFuncSetAttribute(attn_mma,
                         cudaFuncAttributeMaxDynamicSharedMemorySize, ATTN_BYTES);
    cudaFuncSetAttribute(gemm_tf32,
                         cudaFuncAttributeMaxDynamicSharedMemorySize, GEMM_SMEM);

    // 0) pre-round inputs to tf32 (single fused launch)
    round3_tf32<<<(ROUND_TOTAL4 + 255) / 256, 256>>>(
        x, xr_p, w_attn, war_p, w_proj, wpr_p);

    // 1) QKV = Xr @ W_attn_r + b_attn     [2048, 3072]  (mode 1: bias + tf32 round)
    gemm_tf32<<<dim3(QKVN / 128, SEQ / 64, 1), 128, GEMM_SMEM>>>(
        xr_p, war_p, b_attn, qkv_p, SEQ, QKVN, HID, HID, 1);

    // 2) causal flash attention -> g_attn [2048, 1024]  (epilogue rounds to tf32)
    attn_mma<<<dim3(SEQ / 64, NH), 128, ATTN_BYTES>>>(qkv_p, attn_p);

    // 3) proj partials: split-K=2 over z   (mode 2: raw partials, KS=512)
    gemm_tf32<<<dim3(HID / 128, SEQ / 64, 2), 128, GEMM_SMEM>>>(
        attn_p, wpr_p, b_proj, pp_p, SEQ, HID, HID, HID / 2, 2);

    // 4) out = p0 + p1 + b_proj
    fixup_proj<<<(SEQ * HID / 4 + 255) / 256, 256>>>(pp_p, b_proj, out);
}

// round 17
// speedup vs baseline: 1.0930x; 1.0602x over previous
#include <cuda_runtime.h>
#include <cuda_bf16.h>
#include <cstdint>

// Problem constants
#define SEQ  2048
#define HID  1024
#define NH   16
#define HD   64
#define QKVN (3 * HID)   // 3072

// Scratch (allocation-free rule: __device__ globals)
__device__ float g_qkv[SEQ * QKVN];        // [2048, 3072]  (tf32-rounded values)
__device__ float g_attn[SEQ * HID];        // [2048, 1024]  (tf32-rounded values)
__device__ float g_xr[SEQ * HID];          // x rounded to tf32
__device__ float g_war[HID * QKVN];        // w_attn rounded to tf32
__device__ float g_wpr[HID * HID];         // w_proj rounded to tf32

// ===========================================================================
// Helpers
// ===========================================================================
__device__ __forceinline__ uint32_t smem_u32(const void* p) {
    uint32_t a;
    asm("{ .reg .u64 t; cvta.to.shared.u64 t, %1; cvt.u32.u64 %0, t; }" : "=r"(a) : "l"(p));
    return a;
}
__device__ __forceinline__ uint32_t f2tf32(float v) {
    uint32_t r;
    asm("cvt.rna.tf32.f32 %0, %1;" : "=r"(r) : "f"(v));
    return r;
}
__device__ __forceinline__ float tf32v(float v) {
    return __uint_as_float(f2tf32(v));
}
__device__ __forceinline__ void mma_tf32(float d[4],
                                         uint32_t a0, uint32_t a1, uint32_t a2, uint32_t a3,
                                         uint32_t b0, uint32_t b1) {
    asm volatile(
        "mma.sync.aligned.m16n8k8.row.col.f32.tf32.tf32.f32 "
        "{%0,%1,%2,%3}, {%4,%5,%6,%7}, {%8,%9}, {%0,%1,%2,%3};"
        : "+f"(d[0]), "+f"(d[1]), "+f"(d[2]), "+f"(d[3])
        : "r"(a0), "r"(a1), "r"(a2), "r"(a3), "r"(b0), "r"(b1));
}
#define CP_ASYNC16(dst_u32, src_ptr) \
    asm volatile("cp.async.cg.shared.global [%0], [%1], 16;" :: "r"(dst_u32), "l"(src_ptr))
#define CP_COMMIT() asm volatile("cp.async.commit_group;" ::: "memory")
#define CP_WAIT1()  asm volatile("cp.async.wait_group 1;" ::: "memory")
#define CP_WAIT0()  asm volatile("cp.async.wait_group 0;" ::: "memory")

// ===========================================================================
// Fused elementwise tf32 rounding for x / w_attn / w_proj (one launch)
// ===========================================================================
#define XR_N4  (SEQ * HID / 4)
#define WAR_N4 (HID * QKVN / 4)
#define WPR_N4 (HID * HID / 4)
#define ROUND_TOTAL4 (XR_N4 + WAR_N4 + WPR_N4)

__global__ __launch_bounds__(256) void round3_tf32(
    const float* __restrict__ a, float* __restrict__ ar,
    const float* __restrict__ b, float* __restrict__ br,
    const float* __restrict__ c, float* __restrict__ cr)
{
    int i = blockIdx.x * 256 + threadIdx.x;
    const float* src; float* dst; int idx;
    if (i < XR_N4)                 { src = a; dst = ar; idx = i; }
    else if (i < XR_N4 + WAR_N4)   { src = b; dst = br; idx = i - XR_N4; }
    else if (i < ROUND_TOTAL4)     { src = c; dst = cr; idx = i - XR_N4 - WAR_N4; }
    else return;
    float4 v = *(const float4*)(src + (size_t)idx * 4);
    float4 w;
    w.x = tf32v(v.x); w.y = tf32v(v.y); w.z = tf32v(v.z); w.w = tf32v(v.w);
    *(float4*)(dst + (size_t)idx * 4) = w;
}

// ===========================================================================
// tf32 mma.sync GEMM (R12-proven): C = A @ B + bias, B row-major.
// CTA tile 64x128, 128 threads (4 warps 2x2), warp tile 32x64.
// 2-stage cp.async double buffer. 4 CTAs/SM via 128-reg cap.
// ===========================================================================
#define LDA 36
#define LDB 136
#define A_STAGE (64 * LDA)      // floats
#define B_STAGE (32 * LDB)
#define GEMM_SMEM ((2 * (A_STAGE + B_STAGE)) * 4)

__global__ __launch_bounds__(128, 4)
void gemm_tf32(const float* __restrict__ A, const float* __restrict__ B,
               const float* __restrict__ bias, float* __restrict__ C,
               int M, int N, int K, int round_out)
{
    extern __shared__ float smem[];
    float* As = smem;                      // [2][A_STAGE]
    float* Bs = smem + 2 * A_STAGE;        // [2][B_STAGE]
    const uint32_t as_u32 = smem_u32(As);
    const uint32_t bs_u32 = smem_u32(Bs);

    const int tid  = threadIdx.x;
    const int wid  = tid >> 5;
    const int lane = tid & 31;
    const int g = lane >> 2;
    const int t = lane & 3;
    const int wy = wid >> 1;                // 0..1 (M)
    const int wx = wid & 1;                 // 0..1 (N)
    const int row0 = blockIdx.y * 64;
    const int col0 = blockIdx.x * 128;
    const int NS = K >> 5;

    const float* Ag = A + (size_t)row0 * K;
    const float* Bg = B + col0;

    auto copy_stage = [&](int s, int buf) {
        const int k0 = s * 32;
        // A: 64 rows x 8 float4 = 512 -> 4 per thread
#pragma unroll
        for (int u = 0; u < 4; u++) {
            int idx = u * 128 + tid;
            int row = idx >> 3;
            int c4  = idx & 7;
            CP_ASYNC16(as_u32 + (buf * A_STAGE + row * LDA + c4 * 4) * 4,
                       Ag + (size_t)row * K + k0 + c4 * 4);
        }
        // B: 32 rows x 32 float4 = 1024 -> 8 per thread
#pragma unroll
        for (int u = 0; u < 8; u++) {
            int idx = u * 128 + tid;
            int row = idx >> 5;
            int c4  = idx & 31;
            CP_ASYNC16(bs_u32 + (buf * B_STAGE + row * LDB + c4 * 4) * 4,
                       Bg + (size_t)(k0 + row) * N + c4 * 4);
        }
    };

    float acc[2][8][4];
#pragma unroll
    for (int mt = 0; mt < 2; mt++)
#pragma unroll
        for (int nt = 0; nt < 8; nt++)
#pragma unroll
            for (int r = 0; r < 4; r++) acc[mt][nt][r] = 0.f;

    copy_stage(0, 0);
    CP_COMMIT();

    for (int s = 0; s < NS; s++) {
        const int buf = s & 1;
        if (s + 1 < NS) {
            copy_stage(s + 1, buf ^ 1);
            CP_COMMIT();
            CP_WAIT1();
        } else {
            CP_WAIT0();
        }
        __syncthreads();

        const float* Ab = As + buf * A_STAGE;
        const float* Bb = Bs + buf * B_STAGE;

#pragma unroll
        for (int ks = 0; ks < 4; ks++) {
            const int kk = ks * 8;
            uint32_t af[2][4];
#pragma unroll
            for (int mt = 0; mt < 2; mt++) {
                const float* pa = Ab + (wy * 32 + mt * 16 + g) * LDA + kk + t;
                af[mt][0] = __float_as_uint(pa[0]);
                af[mt][1] = __float_as_uint(pa[8 * LDA]);
                af[mt][2] = __float_as_uint(pa[4]);
                af[mt][3] = __float_as_uint(pa[8 * LDA + 4]);
            }
            uint32_t bf[8][2];
#pragma unroll
            for (int nt = 0; nt < 8; nt++) {
                const float* pb = Bb + (kk + t) * LDB + wx * 64 + nt * 8 + g;
                bf[nt][0] = __float_as_uint(pb[0]);
                bf[nt][1] = __float_as_uint(pb[4 * LDB]);
            }
#pragma unroll
            for (int mt = 0; mt < 2; mt++)
#pragma unroll
                for (int nt = 0; nt < 8; nt++)
                    mma_tf32(acc[mt][nt], af[mt][0], af[mt][1], af[mt][2], af[mt][3],
                             bf[nt][0], bf[nt][1]);
        }
        __syncthreads();
    }

#pragma unroll
    for (int mt = 0; mt < 2; mt++) {
        int m = row0 + wy * 32 + mt * 16 + g;
#pragma unroll
        for (int nt = 0; nt < 8; nt++) {
            int n = col0 + wx * 64 + nt * 8 + 2 * t;
            float2 o0, o1;
            o0.x = acc[mt][nt][0] + bias[n];
            o0.y = acc[mt][nt][1] + bias[n + 1];
            o1.x = acc[mt][nt][2] + bias[n];
            o1.y = acc[mt][nt][3] + bias[n + 1];
            if (round_out) {
                o0.x = tf32v(o0.x); o0.y = tf32v(o0.y);
                o1.x = tf32v(o1.x); o1.y = tf32v(o1.y);
            }
            *(float2*)(C + (size_t)m * N + n)       = o0;
            *(float2*)(C + (size_t)(m + 8) * N + n) = o1;
        }
    }
}

// ===========================================================================
// Flash attention, tf32 mma.sync (R12 structure) with SPLIT K/V commit groups:
// K group awaited before S-compute; V group awaited only after softmax, so
// V's load latency is hidden behind S MMAs + mask + softmax.
// CTA = (head, 64 q rows), 4 warps. Q persistent fragments, shfl-transposed P.
// ===========================================================================
#define ALD 68                       // K lead dim (S-phase B reads: bank 4g+t)
#define VLD 72                       // V lead dim (PV B reads: bank 8t+g)
#define KP_FLOATS (128 * ALD)        // K tile (also Q staging area before loop)
#define AT_V  KP_FLOATS
#define ATTN_FLOATS (KP_FLOATS + 128 * VLD)
#define ATTN_BYTES  (ATTN_FLOATS * 4)

__global__ __launch_bounds__(128)
void attn_mma(const float* __restrict__ qkv, float* __restrict__ out)
{
    extern __shared__ float sm[];
    float* KPs = sm;               // K tile (Q staged here once before loop)
    float* Vs  = sm + AT_V;
    const uint32_t kp_u32 = smem_u32(KPs);
    const uint32_t vs_u32 = smem_u32(Vs);

    const int tid  = threadIdx.x;
    const int lane = tid & 31;
    const int wid  = tid >> 5;     // 0..3
    const int g = lane >> 2;
    const int t = lane & 3;
    const int h  = blockIdx.y;
    const int qb = (int)gridDim.x - 1 - (int)blockIdx.x;   // heavy CTAs first
    const int q0 = qb * 64;
    const int rowbase = wid * 16;
    const int nkb = (qb >> 1) + 1;

    // ---- stage Q into KPs (x0.125 exponent-only: stays valid tf32) ----
#pragma unroll
    for (int u = 0; u < 8; u++) {
        int i4 = u * 128 + tid;
        int r = i4 >> 4;
        int d = (i4 & 15) * 4;
        float4 v = *(const float4*)(qkv + (size_t)(q0 + r) * QKVN + h * HD + d);
        v.x *= 0.125f; v.y *= 0.125f; v.z *= 0.125f; v.w *= 0.125f;
        *(float4*)&KPs[r * ALD + d] = v;
    }
    __syncthreads();

    uint32_t qf[8][4];
#pragma unroll
    for (int ks = 0; ks < 8; ks++) {
        const float* pa = KPs + (rowbase + g) * ALD + ks * 8 + t;
        qf[ks][0] = __float_as_uint(pa[0]);
        qf[ks][1] = __float_as_uint(pa[8 * ALD]);
        qf[ks][2] = __float_as_uint(pa[4]);
        qf[ks][3] = __float_as_uint(pa[8 * ALD + 4]);
    }

    float O[8][4];
    float m0 = -1e30f, m1 = -1e30f, l0 = 0.f, l1 = 0.f;
#pragma unroll
    for (int nt = 0; nt < 8; nt++)
#pragma unroll
        for (int r = 0; r < 4; r++) O[nt][r] = 0.f;

    for (int kb = 0; kb < nkb; kb++) {
        __syncthreads();   // prior consumers of KPs/Vs done (incl. qf reads @kb=0)

        // ---- issue K as group 1, V as group 2 (values already tf32) ----
#pragma unroll
        for (int u = 0; u < 16; u++) {
            int i4 = u * 128 + tid;
            int r = i4 >> 4;
            int d = (i4 & 15) * 4;
            CP_ASYNC16(kp_u32 + (r * ALD + d) * 4,
                       qkv + (size_t)(kb * 128 + r) * QKVN + h * HD + HID + d);
        }
        CP_COMMIT();       // group: K
#pragma unroll
        for (int u = 0; u < 16; u++) {
            int i4 = u * 128 + tid;
            int r = i4 >> 4;
            int d = (i4 & 15) * 4;
            CP_ASYNC16(vs_u32 + (r * VLD + d) * 4,
                       qkv + (size_t)(kb * 128 + r) * QKVN + h * HD + 2 * HID + d);
        }
        CP_COMMIT();       // group: V

        CP_WAIT1();        // K resident (V may still be in flight)
        __syncthreads();

        // ---- S = Q @ K^T  (V load overlaps this + softmax) ----
        float S[16][4];
#pragma unroll
        for (int nt = 0; nt < 16; nt++)
#pragma unroll
            for (int r = 0; r < 4; r++) S[nt][r] = 0.f;

#pragma unroll
        for (int ks = 0; ks < 8; ks++) {
#pragma unroll
            for (int nt = 0; nt < 16; nt++) {
                const float* pb = KPs + (nt * 8 + g) * ALD + ks * 8 + t;
                uint32_t b0 = __float_as_uint(pb[0]);
                uint32_t b1 = __float_as_uint(pb[4]);
                mma_tf32(S[nt], qf[ks][0], qf[ks][1], qf[ks][2], qf[ks][3], b0, b1);
            }
        }

        // ---- causal mask (last k-block only) ----
        if (kb == nkb - 1) {
            const int r0 = q0 + rowbase + g, r1 = r0 + 8;
            const int cb = kb * 128;
#pragma unroll
            for (int nt = 0; nt < 16; nt++) {
                int c = cb + nt * 8 + 2 * t;
                if (c     > r0) S[nt][0] = -1e30f;
                if (c + 1 > r0) S[nt][1] = -1e30f;
                if (c     > r1) S[nt][2] = -1e30f;
                if (c + 1 > r1) S[nt][3] = -1e30f;
            }
        }

        // ---- online softmax ----
        float mt0 = -1e30f, mt1 = -1e30f;
#pragma unroll
        for (int nt = 0; nt < 16; nt++) {
            mt0 = fmaxf(mt0, fmaxf(S[nt][0], S[nt][1]));
            mt1 = fmaxf(mt1, fmaxf(S[nt][2], S[nt][3]));
        }
        mt0 = fmaxf(mt0, __shfl_xor_sync(0xffffffffu, mt0, 1));
        mt0 = fmaxf(mt0, __shfl_xor_sync(0xffffffffu, mt0, 2));
        mt1 = fmaxf(mt1, __shfl_xor_sync(0xffffffffu, mt1, 1));
        mt1 = fmaxf(mt1, __shfl_xor_sync(0xffffffffu, mt1, 2));
        float mn0 = fmaxf(m0, mt0), mn1 = fmaxf(m1, mt1);
        float al0 = __expf(m0 - mn0), al1 = __expf(m1 - mn1);
        float ps0 = 0.f, ps1 = 0.f;
#pragma unroll
        for (int nt = 0; nt < 16; nt++) {
            float p00 = __expf(S[nt][0] - mn0);
            float p01 = __expf(S[nt][1] - mn0);
            float p10 = __expf(S[nt][2] - mn1);
            float p11 = __expf(S[nt][3] - mn1);
            S[nt][0] = p00; S[nt][1] = p01; S[nt][2] = p10; S[nt][3] = p11;
            ps0 += p00 + p01;
            ps1 += p10 + p11;
        }
        ps0 += __shfl_xor_sync(0xffffffffu, ps0, 1);
        ps0 += __shfl_xor_sync(0xffffffffu, ps0, 2);
        ps1 += __shfl_xor_sync(0xffffffffu, ps1, 1);
        ps1 += __shfl_xor_sync(0xffffffffu, ps1, 2);
        l0 = l0 * al0 + ps0;  m0 = mn0;
        l1 = l1 * al1 + ps1;  m1 = mn1;
#pragma unroll
        for (int nt = 0; nt < 8; nt++) {
            O[nt][0] *= al0; O[nt][1] *= al0;
            O[nt][2] *= al1; O[nt][3] *= al1;
        }

        CP_WAIT0();        // V resident
        __syncthreads();

        // ---- O += P @ V : A-frag via shfl transpose of S (no smem, no sync) ----
        {
            const int src0 = (lane & 28) | (t >> 1);
            const int src1 = src0 | 2;
            const bool odd = (t & 1);
#pragma unroll
            for (int ks = 0; ks < 16; ks++) {
                float p0 = tf32v(S[ks][0]), p1 = tf32v(S[ks][1]);
                float p2 = tf32v(S[ks][2]), p3 = tf32v(S[ks][3]);
                float v00 = __shfl_sync(0xffffffffu, p0, src0);
                float v01 = __shfl_sync(0xffffffffu, p1, src0);
                float v02 = __shfl_sync(0xffffffffu, p2, src0);
                float v03 = __shfl_sync(0xffffffffu, p3, src0);
                float v10 = __shfl_sync(0xffffffffu, p0, src1);
                float v11 = __shfl_sync(0xffffffffu, p1, src1);
                float v12 = __shfl_sync(0xffffffffu, p2, src1);
                float v13 = __shfl_sync(0xffffffffu, p3, src1);
                uint32_t a0 = __float_as_uint(odd ? v01 : v00);
                uint32_t a1 = __float_as_uint(odd ? v03 : v02);
                uint32_t a2 = __float_as_uint(odd ? v11 : v10);
                uint32_t a3 = __float_as_uint(odd ? v13 : v12);
#pragma unroll
                for (int nt = 0; nt < 8; nt++) {
                    uint32_t b0 = __float_as_uint(Vs[(ks * 8 + t)     * VLD + nt * 8 + g]);
                    uint32_t b1 = __float_as_uint(Vs[(ks * 8 + t + 4) * VLD + nt * 8 + g]);
                    mma_tf32(O[nt], a0, a1, a2, a3, b0, b1);
                }
            }
        }
    }

    // ---- epilogue: normalize, round to tf32 (feeds proj GEMM) ----
    float inv0 = 1.0f / l0, inv1 = 1.0f / l1;
#pragma unroll
    for (int nt = 0; nt < 8; nt++) {
        int c = h * HD + nt * 8 + 2 * t;
        float2 o0, o1;
        o0.x = tf32v(O[nt][0] * inv0); o0.y = tf32v(O[nt][1] * inv0);
        o1.x = tf32v(O[nt][2] * inv1); o1.y = tf32v(O[nt][3] * inv1);
        *(float2*)(out + (size_t)(q0 + rowbase + g)     * HID + c) = o0;
        *(float2*)(out + (size_t)(q0 + rowbase + g + 8) * HID + c) = o1;
    }
}

// ---------------------------------------------------------------------------
// Launch
// ---------------------------------------------------------------------------
extern "C" void kernel_launch(void* const* d_in, const int* in_sizes, int n_in,
                              void* d_out, int out_size)
{
    const float* x      = (const float*)d_in[0];
    const float* w_attn = (const float*)d_in[1];
    const float* b_attn = (const float*)d_in[2];
    const float* w_proj = (const float*)d_in[3];
    const float* b_proj = (const float*)d_in[4];
    float* out = (float*)d_out;

    float *qkv_p, *attn_p, *xr_p, *war_p, *wpr_p;
    cudaGetSymbolAddress((void**)&qkv_p,  g_qkv);
    cudaGetSymbolAddress((void**)&attn_p, g_attn);
    cudaGetSymbolAddress((void**)&xr_p,   g_xr);
    cudaGetSymbolAddress((void**)&war_p,  g_war);
    cudaGetSymbolAddress((void**)&wpr_p,  g_wpr);

    cudaFuncSetAttribute(attn_mma,
                         cudaFuncAttributeMaxDynamicSharedMemorySize, ATTN_BYTES);
    cudaFuncSetAttribute(gemm_tf32,
                         cudaFuncAttributeMaxDynamicSharedMemorySize, GEMM_SMEM);

    // 0) pre-round inputs to tf32 (single fused launch)
    round3_tf32<<<(ROUND_TOTAL4 + 255) / 256, 256>>>(
        x, xr_p, w_attn, war_p, w_proj, wpr_p);

    // 1) QKV = Xr @ W_attn_r + b_attn     [2048, 3072]  (epilogue rounds to tf32)
    gemm_tf32<<<dim3(QKVN / 128, SEQ / 64), 128, GEMM_SMEM>>>(
        xr_p, war_p, b_attn, qkv_p, SEQ, QKVN, HID, 1);

    // 2) causal flash attention -> g_attn [2048, 1024]  (epilogue rounds to tf32)
    attn_mma<<<dim3(SEQ / 64, NH), 128, ATTN_BYTES>>>(qkv_p, attn_p);

    // 3) out = attn @ W_proj_r + b_proj   [2048, 1024]
    gemm_tf32<<<dim3(HID / 128, SEQ / 64), 128, GEMM_SMEM>>>(
        attn_p, wpr_p, b_proj, out, SEQ, HID, HID, 0);
}